// round 13
// baseline (speedup 1.0000x reference)
#include <cuda_runtime.h>
#include <cstdint>

// Embedding gather, single-kernel filter-and-gather.
// weight: [1'000'000, 128] f32 (512 MB), index: [2'097'152] i32, out: 1 GB.
//
// NB=32 L2 slices of the table (16 MB each). grid = 32 buckets x 1024 blocks;
// blocks are bucket-contiguous so resident blocks share one slice in L2 and
// repeat rows (~57% of draws) hit in L2 (DRAM reads ~450 MB, not 1045 MB).
//
// Each block re-reads its 2048-entry index slice (8 MB index is L2-resident),
// filters for its bucket (~64 matches) with ballot-aggregated compaction
// (1 shared atomic per warp-step instead of 8 serialized per-thread atomics),
// then gathers rows with the half-warp 256-bit ld/st pattern.

static constexpr int NB       = 32;
static constexpr int BSHIFT   = 15;               // 2^15 rows per bucket
static constexpr int BPB_LOG2 = 10;               // 1024 blocks per bucket
static constexpr int BPB      = 1 << BPB_LOG2;
static constexpr int IPB      = 2048;             // index slice per block
static constexpr int C        = 16;               // 32 B chunks per 512 B row
static constexpr int LCAP     = 256;              // shared list capacity

__device__ __forceinline__ ulonglong4 ldg256_evict_last(const ulonglong4* p) {
    ulonglong4 v;
    asm volatile("ld.global.nc.L2::evict_last.v4.u64 {%0,%1,%2,%3}, [%4];"
                 : "=l"(v.x), "=l"(v.y), "=l"(v.z), "=l"(v.w)
                 : "l"(p));
    return v;
}

__device__ __forceinline__ void stg256_cs(ulonglong4* p, const ulonglong4& v) {
    asm volatile("st.global.cs.v4.u64 [%0], {%1,%2,%3,%4};"
                 :: "l"(p), "l"(v.x), "l"(v.y), "l"(v.z), "l"(v.w)
                 : "memory");
}

// Statistically unreachable (list cap 256 vs mean 64, sigma ~8); kept correct
// but outside the hot path's register budget.
__device__ __noinline__ void overflow_copy_row(
    const ulonglong4* __restrict__ weight,
    ulonglong4*       __restrict__ out,
    int idx, long long pos)
{
    const ulonglong4* src = &weight[(size_t)idx * C];
    ulonglong4*       dst = &out[pos * C];
#pragma unroll
    for (int c = 0; c < C; c++)
        stg256_cs(&dst[c], ldg256_evict_last(&src[c]));
}

__global__ __launch_bounds__(256, 7) void gather_kernel(
    const ulonglong4* __restrict__ weight,
    const int4*       __restrict__ index4,
    ulonglong4*       __restrict__ out,
    int n_index)
{
    __shared__ int2 list[LCAP];
    __shared__ int  count;

    const int bucket = blockIdx.x >> BPB_LOG2;
    const int lbid   = blockIdx.x & (BPB - 1);
    const int tid    = threadIdx.x;
    const int lane   = tid & 31;
    const unsigned lt_mask = (1u << lane) - 1;

    if (tid == 0) count = 0;
    __syncthreads();

    // ---- Filter phase: scan this block's 2048-index slice (L2-resident). ----
    // n_index == BPB * IPB exactly, so every thread of every block is active
    // and full-mask warp collectives are safe.
    const long long tpos = (long long)lbid * IPB + tid * 8;
    {
        int4 a = __ldg(&index4[tpos / 4]);
        int4 b = __ldg(&index4[tpos / 4 + 1]);
        int idx[8] = {a.x, a.y, a.z, a.w, b.x, b.y, b.z, b.w};
#pragma unroll
        for (int i = 0; i < 8; i++) {
            const bool m = (idx[i] >> BSHIFT) == bucket;
            const unsigned mask = __ballot_sync(0xffffffffu, m);
            if (mask) {
                int base = 0;
                if (lane == 0) base = atomicAdd(&count, __popc(mask));
                base = __shfl_sync(0xffffffffu, base, 0);
                if (m) {
                    const int slot = base + __popc(mask & lt_mask);
                    if (slot < LCAP)
                        list[slot] = make_int2((int)(tpos + i), idx[i]);
                    else
                        overflow_copy_row(weight, out, idx[i], tpos + i);
                }
            }
        }
    }
    __syncthreads();

    int cnt = count;
    if (cnt > LCAP) cnt = LCAP;

    // ---- Gather phase: half-warp / 256-bit pattern, 2 pairs per pass. ----
    // Warp handles 4 entries as 2 (even,odd) pairs; a half-warp (16 lanes x
    // 32 B) moves one 512 B row. 8 warps x 4 entries = 32 per pass.
    const int sub  = lane >> 4;                   // 0: even entry, 1: odd entry
    const int l16  = lane & 15;
    const int warp = tid >> 5;

    for (int base = warp * 4; base < cnt; base += 8 * 4) {
        int2 ent[2];
#pragma unroll
        for (int p = 0; p < 2; p++) {
            int e = base + 2 * p + sub;
            ent[p] = (e < cnt) ? list[e] : make_int2(0, 0);
        }

        ulonglong4 v[2];
#pragma unroll
        for (int p = 0; p < 2; p++)
            v[p] = ldg256_evict_last(&weight[(size_t)ent[p].y * C + l16]);

#pragma unroll
        for (int p = 0; p < 2; p++) {
            int e = base + 2 * p + sub;
            if (e < cnt)
                stg256_cs(&out[(size_t)ent[p].x * C + l16], v[p]);
        }
    }
}

extern "C" void kernel_launch(void* const* d_in, const int* in_sizes, int n_in,
                              void* d_out, int out_size)
{
    const ulonglong4* weight = (const ulonglong4*)d_in[0];
    const int4*       index4 = (const int4*)d_in[1];
    ulonglong4*       out    = (ulonglong4*)d_out;

    const int n_index = in_sizes[1];              // 2,097,152 = 1024 * 2048

    gather_kernel<<<NB << BPB_LOG2, 256>>>(weight, index4, out, n_index);
}